// round 2
// baseline (speedup 1.0000x reference)
#include <cuda_runtime.h>

#define B_ 1024
#define T_ 512
#define C_ 64
#define START_ 62
#define STOP_ 63
#define NEG_INF_ (-10000.0f)

// per-batch (log_Z - gold) scratch
__device__ float g_part[B_];

__global__ void __launch_bounds__(64) crf_fwd(const float* __restrict__ em,
                                              const float* __restrict__ trans,
                                              const int* __restrict__ tags,
                                              const int* __restrict__ mask)
{
    const int b = blockIdx.x;
    const int j = threadIdx.x;
    const int lane = j & 31;
    const int wid = j >> 5;

    __shared__ float s_p[2][C_];
    __shared__ float s_wred[2];
    __shared__ int   s_prev;
    __shared__ float s_gold;

    // Register-resident column of exp(transitions): e[i] = exp(trans[i][j])
    float e[C_];
#pragma unroll
    for (int i = 0; i < C_; ++i) e[i] = __expf(trans[i * C_ + j]);

    if (j == 0) { s_prev = START_; s_gold = 0.0f; }

    float alpha = (j == START_) ? 0.0f : NEG_INF_;

    const float* emb = em   + (size_t)b * T_ * C_;
    const int*   tgb = tags + (size_t)b * T_;
    const int*   mkb = mask + (size_t)b * T_;

    // depth-1 prefetch
    float emit = emb[j];
    int   tg   = tgb[0];
    int   mk   = mkb[0];

    __syncthreads();   // covers s_prev/s_gold init

    for (int t = 0; t < T_; ++t) {
        float emit_n = 0.0f; int tg_n = 0; int mk_n = 0;
        if (t + 1 < T_) {
            emit_n = emb[(size_t)(t + 1) * C_ + j];
            tg_n   = tgb[t + 1];
            mk_n   = mkb[t + 1];
        }

        // ---- block max of alpha (warp shfl + 2-way shared exchange) ----
        float m = alpha;
#pragma unroll
        for (int o = 16; o > 0; o >>= 1)
            m = fmaxf(m, __shfl_xor_sync(0xffffffffu, m, o));
        if (lane == 0) s_wred[wid] = m;
        __syncthreads();
        m = fmaxf(s_wred[0], s_wred[1]);

        const int buf = t & 1;
        s_p[buf][j] = __expf(alpha - m);

        // ---- gold score: thread owning tag_t contributes (exclusive writer) ----
        if (mk && j == tg) {
            int pv = s_prev;
            s_gold += emit + trans[pv * C_ + j];
            s_prev = j;
        }
        __syncthreads();

        // ---- matvec: s_j = sum_i p_i * E_ij  (float4 loads, 4 accumulators) ----
        float s0 = 0.f, s1 = 0.f, s2 = 0.f, s3 = 0.f;
#pragma unroll
        for (int i = 0; i < C_; i += 4) {
            float4 pv = *reinterpret_cast<const float4*>(&s_p[buf][i]);
            s0 = fmaf(pv.x, e[i + 0], s0);
            s1 = fmaf(pv.y, e[i + 1], s1);
            s2 = fmaf(pv.z, e[i + 2], s2);
            s3 = fmaf(pv.w, e[i + 3], s3);
        }
        float s = fmaxf((s0 + s1) + (s2 + s3), 1e-30f);

        float na = m + __logf(s) + emit;
        alpha = mk ? na : alpha;

        emit = emit_n; tg = tg_n; mk = mk_n;
    }

    // ---- final: alpha += trans[:, STOP]; log-sum-exp over j ----
    float val = alpha + trans[j * C_ + STOP_];

    float m = val;
#pragma unroll
    for (int o = 16; o > 0; o >>= 1)
        m = fmaxf(m, __shfl_xor_sync(0xffffffffu, m, o));
    if (lane == 0) s_wred[wid] = m;
    __syncthreads();
    m = fmaxf(s_wred[0], s_wred[1]);

    float ex = __expf(val - m);
#pragma unroll
    for (int o = 16; o > 0; o >>= 1)
        ex += __shfl_xor_sync(0xffffffffu, ex, o);
    __syncthreads();                 // s_wred reuse safety
    if (lane == 0) s_wred[wid] = ex;
    __syncthreads();

    if (j == 0) {
        float logZ = m + __logf(s_wred[0] + s_wred[1]);
        float gold = s_gold + trans[s_prev * C_ + STOP_];
        g_part[b] = logZ - gold;
    }
}

// Deterministic fixed-order mean reduction (double accumulation).
__global__ void crf_reduce(float* __restrict__ out)
{
    __shared__ double sh[256];
    const int tid = threadIdx.x;
    double s = 0.0;
    for (int i = tid; i < B_; i += 256) s += (double)g_part[i];
    sh[tid] = s;
    __syncthreads();
    for (int o = 128; o > 0; o >>= 1) {
        if (tid < o) sh[tid] += sh[tid + o];
        __syncthreads();
    }
    if (tid == 0) out[0] = (float)(sh[0] / (double)B_);
}

extern "C" void kernel_launch(void* const* d_in, const int* in_sizes, int n_in,
                              void* d_out, int out_size)
{
    const float* em    = (const float*)d_in[0];
    const float* trans = (const float*)d_in[1];
    const int*   tags  = (const int*)d_in[2];
    const int*   mask  = (const int*)d_in[3];

    crf_fwd<<<B_, C_>>>(em, trans, tags, mask);
    crf_reduce<<<1, 256>>>((float*)d_out);
    (void)in_sizes; (void)n_in; (void)out_size;
}

// round 3
// speedup vs baseline: 1.5726x; 1.5726x over previous
#include <cuda_runtime.h>

#define B_ 1024
#define T_ 512
#define C_ 64
#define START_ 62
#define STOP_ 63
#define NEG_INF_ (-10000.0f)

// per-batch (log_Z - gold) scratch + completion ticket
__device__ float g_part[B_];
__device__ unsigned int g_done = 0;

__device__ __forceinline__ unsigned long long fma2(unsigned long long a,
                                                   unsigned long long b,
                                                   unsigned long long c)
{
    unsigned long long d;
    asm("fma.rn.f32x2 %0, %1, %2, %3;" : "=l"(d) : "l"(a), "l"(b), "l"(c));
    return d;
}
__device__ __forceinline__ unsigned long long pack2(float lo, float hi)
{
    unsigned long long d;
    asm("mov.b64 %0, {%1, %2};" : "=l"(d) : "f"(lo), "f"(hi));
    return d;
}
__device__ __forceinline__ float2 unpack2(unsigned long long v)
{
    float lo, hi;
    asm("mov.b64 {%0, %1}, %2;" : "=f"(lo), "=f"(hi) : "l"(v));
    return make_float2(lo, hi);
}

__global__ void __launch_bounds__(64) crf_fwd(const float* __restrict__ em,
                                              const float* __restrict__ trans,
                                              const int* __restrict__ tags,
                                              const int* __restrict__ mask,
                                              float* __restrict__ out)
{
    const int b = blockIdx.x;
    const int j = threadIdx.x;
    const int lane = j & 31;
    const int wid = j >> 5;

    __shared__ __align__(16) float s_p[2][C_];
    __shared__ float s_ref[2];
    __shared__ float s_wred[2];
    __shared__ int   s_prev;
    __shared__ float s_gold;
    __shared__ int   s_last;

    // e2[k] = {exp(trans[2k][j]), exp(trans[2k+1][j])} packed f32x2
    unsigned long long e2[C_ / 2];
#pragma unroll
    for (int k = 0; k < C_ / 2; ++k)
        e2[k] = pack2(__expf(trans[(2 * k) * C_ + j]),
                      __expf(trans[(2 * k + 1) * C_ + j]));

    if (j == 0) { s_prev = START_; s_gold = 0.0f; }

    float alpha = (j == START_) ? 0.0f : NEG_INF_;
    float ref   = 0.0f;   // block-uniform shift; exact cancellation, any value ok

    const float* emb = em   + (size_t)b * T_ * C_;
    const int*   tgb = tags + (size_t)b * T_;
    const int*   mkb = mask + (size_t)b * T_;

    // depth-4 prefetch ring (~800 cyc distance >= 577 cyc DRAM latency)
    float embuf[4]; int tgbuf[4], mkbuf[4];
#pragma unroll
    for (int k = 0; k < 4; ++k) {
        embuf[k] = emb[k * C_ + j];
        tgbuf[k] = tgb[k];
        mkbuf[k] = mkb[k];
    }

    __syncthreads();   // covers s_prev/s_gold init

#pragma unroll 4
    for (int t = 0; t < T_; ++t) {
        const int sl  = t & 3;
        const int buf = t & 1;
        const float emit = embuf[sl];
        const int   tg   = tgbuf[sl];
        const int   mk   = mkbuf[sl];

        // issue prefetch for t+4 early (off the critical path)
        float e_n = 0.0f; int tg_n = 0, mk_n = 0;
        if (t + 4 < T_) {
            e_n  = emb[(size_t)(t + 4) * C_ + j];
            tg_n = tgb[t + 4];
            mk_n = mkb[t + 4];
        }

        // publish p-vector and the (lagged) reference
        s_p[buf][j] = __expf(alpha - ref);
        if (j == 0) s_ref[buf] = (t == 0) ? 0.0f : alpha;
        __syncthreads();

        // gold score: exclusive writer, ordered by the barriers
        if (mk && j == tg) {
            s_gold += emit + trans[s_prev * C_ + j];
            s_prev = j;
        }

        // matvec: s_j = sum_i p_i * E_ij  via packed f32x2 FMA
        const ulonglong2* ps = reinterpret_cast<const ulonglong2*>(s_p[buf]);
        unsigned long long a0 = 0ull, a1 = 0ull, a2 = 0ull, a3 = 0ull;
#pragma unroll
        for (int k = 0; k < 16; k += 2) {
            ulonglong2 p0 = ps[k];
            ulonglong2 p1 = ps[k + 1];
            a0 = fma2(p0.x, e2[2 * k + 0], a0);
            a1 = fma2(p0.y, e2[2 * k + 1], a1);
            a2 = fma2(p1.x, e2[2 * k + 2], a2);
            a3 = fma2(p1.y, e2[2 * k + 3], a3);
        }
        float2 f0 = unpack2(a0), f1 = unpack2(a1), f2 = unpack2(a2), f3 = unpack2(a3);
        float s = ((f0.x + f0.y) + (f1.x + f1.y)) + ((f2.x + f2.y) + (f3.x + f3.y));
        s = fmaxf(s, 1e-30f);

        const float na = ref + __logf(s) + emit;
        const float ref_n = s_ref[buf];     // after barrier: safe read
        alpha = mk ? na : alpha;
        ref = ref_n;

        embuf[sl] = e_n; tgbuf[sl] = tg_n; mkbuf[sl] = mk_n;
    }

    // ---- final: alpha += trans[:, STOP]; exact log-sum-exp over j ----
    const float val = alpha + trans[j * C_ + STOP_];

    float m = val;
#pragma unroll
    for (int o = 16; o > 0; o >>= 1)
        m = fmaxf(m, __shfl_xor_sync(0xffffffffu, m, o));
    if (lane == 0) s_wred[wid] = m;
    __syncthreads();
    m = fmaxf(s_wred[0], s_wred[1]);

    float ex = __expf(val - m);
#pragma unroll
    for (int o = 16; o > 0; o >>= 1)
        ex += __shfl_xor_sync(0xffffffffu, ex, o);
    __syncthreads();
    if (lane == 0) s_wred[wid] = ex;
    __syncthreads();

    if (j == 0) {
        const float logZ = m + __logf(s_wred[0] + s_wred[1]);
        const float gold = s_gold + trans[s_prev * C_ + STOP_];
        g_part[b] = logZ - gold;
        __threadfence();
        unsigned int v = atomicAdd(&g_done, 1u);
        s_last = (v == (unsigned)(B_ - 1));
    }
    __syncthreads();

    // last block to finish performs the deterministic mean reduction
    if (s_last) {
        __shared__ double sh[C_];
        double acc = 0.0;
        for (int i = j; i < B_; i += C_) acc += (double)g_part[i];  // fixed order
        sh[j] = acc;
        __syncthreads();
        if (j == 0) {
            double tot = 0.0;
            for (int i = 0; i < C_; ++i) tot += sh[i];              // fixed order
            out[0] = (float)(tot / (double)B_);
            g_done = 0;   // reset for next graph replay
        }
    }
}

extern "C" void kernel_launch(void* const* d_in, const int* in_sizes, int n_in,
                              void* d_out, int out_size)
{
    const float* em    = (const float*)d_in[0];
    const float* trans = (const float*)d_in[1];
    const int*   tags  = (const int*)d_in[2];
    const int*   mask  = (const int*)d_in[3];

    crf_fwd<<<B_, C_>>>(em, trans, tags, mask, (float*)d_out);
    (void)in_sizes; (void)n_in; (void)out_size;
}